// round 1
// baseline (speedup 1.0000x reference)
#include <cuda_runtime.h>
#include <math.h>

#define N_NODES 10000
#define N_EDGES 160000
#define HDIM    128
#define NLAYERS 3
#define BN_EPS  1e-5f

// ---------------- device scratch (static, allowed) ----------------
__device__ float g_coords[N_NODES * 3];
__device__ float g_diff[N_EDGES * 3];
__device__ float g_dist[N_EDGES];
__device__ float g_V[N_NODES * HDIM];
__device__ float g_Vraw[N_NODES * HDIM];
__device__ float g_VH[N_NODES * HDIM];
__device__ float g_mi[N_NODES * HDIM];
__device__ float g_accum[N_NODES * 3];
__device__ float g_T1[N_EDGES * HDIM];     // phi_e hidden, reused as phi_x hidden
__device__ float g_mij[N_EDGES * HDIM];
__device__ float g_part[2 * 256 * HDIM];   // BN partial sums
__device__ float g_muinv[2 * HDIM];        // BN mu / inv-std

enum { MODE_PLAIN = 0, MODE_EDGE = 1, MODE_CAT = 2 };

__device__ __forceinline__ float silu_f(float x) { return x / (1.0f + expf(-x)); }
__device__ __forceinline__ float elu_f(float x)  { return x > 0.0f ? x : (expf(x) - 1.0f); }

// ---------------- generic 128-wide GEMM: C[M,128] = act(A[M,K] @ W[K,128] + b)
// MODE_PLAIN: A contiguous row-major [M,K]
// MODE_EDGE : A row r = [ V[src[r]] (128) | V[dst[r]] (128) | dist[r] | ee[r,0..1] ], K=259
// MODE_CAT  : A row r = [ A[r] (128) | A2[r] (128) ], K=256
template <int MODE, bool DO_SILU>
__global__ __launch_bounds__(256) void gemm_k(
    const float* __restrict__ A, const float* __restrict__ A2,
    const float* __restrict__ W, const float* __restrict__ bias,
    float* __restrict__ C, int M, int K,
    const int* __restrict__ srcv, const int* __restrict__ dstv,
    const float* __restrict__ Vg, const float* __restrict__ distv,
    const float* __restrict__ ee)
{
    __shared__ float As[16][128];
    __shared__ float Bs[16][132];

    const int tid  = threadIdx.x;
    const int m0   = blockIdx.x * 128;
    const int arow = tid >> 1;           // 0..127 : row this thread loads
    const int akb  = (tid & 1) * 8;      // k sub-offset 0 / 8
    const int brow = tid >> 4;           // 0..15 : k this thread loads for B
    const int bcol = (tid & 15) * 8;

    const int gm   = m0 + arow;
    const bool mval = (gm < M);

    int es = 0, ed = 0;
    float edist = 0.f, ee0 = 0.f, ee1 = 0.f;
    if (MODE == MODE_EDGE && mval) {
        es = srcv[gm]; ed = dstv[gm];
        edist = distv[gm];
        ee0 = ee[gm * 2 + 0]; ee1 = ee[gm * 2 + 1];
    }

    const int row0 = (tid >> 4) * 8;     // compute-tile row base
    const int col0 = (tid & 15) * 8;     // compute-tile col base

    float acc[8][8];
#pragma unroll
    for (int i = 0; i < 8; i++)
#pragma unroll
        for (int j = 0; j < 8; j++) acc[i][j] = 0.f;

    const int nk = (K + 15) >> 4;
    for (int kt = 0; kt < nk; kt++) {
        const int kbase = kt * 16;

        // load B tile (16 x 128)
        {
            const int gk = kbase + brow;
            if (gk < K) {
                const float* wp = W + (size_t)gk * 128 + bcol;
#pragma unroll
                for (int i = 0; i < 8; i++) Bs[brow][bcol + i] = wp[i];
            } else {
#pragma unroll
                for (int i = 0; i < 8; i++) Bs[brow][bcol + i] = 0.f;
            }
        }

        // load A tile (128 x 16), stored transposed As[k][m]
        if (MODE == MODE_PLAIN) {
#pragma unroll
            for (int i = 0; i < 8; i++) {
                const int gk = kbase + akb + i;
                As[akb + i][arow] = (mval && gk < K) ? A[(size_t)gm * K + gk] : 0.f;
            }
        } else if (MODE == MODE_EDGE) {
#pragma unroll
            for (int i = 0; i < 8; i++) {
                const int gk = kbase + akb + i;
                float v = 0.f;
                if (mval && gk < 259) {
                    if (gk < 128)      v = Vg[(size_t)es * 128 + gk];
                    else if (gk < 256) v = Vg[(size_t)ed * 128 + (gk - 128)];
                    else if (gk == 256) v = edist;
                    else if (gk == 257) v = ee0;
                    else                v = ee1;
                }
                As[akb + i][arow] = v;
            }
        } else { // MODE_CAT, K = 256
#pragma unroll
            for (int i = 0; i < 8; i++) {
                const int gk = kbase + akb + i;
                float v = 0.f;
                if (mval) {
                    v = (gk < 128) ? A[(size_t)gm * 128 + gk]
                                   : A2[(size_t)gm * 128 + (gk - 128)];
                }
                As[akb + i][arow] = v;
            }
        }

        __syncthreads();

#pragma unroll
        for (int kk = 0; kk < 16; kk++) {
            float4 a0 = *(const float4*)&As[kk][row0];
            float4 a1 = *(const float4*)&As[kk][row0 + 4];
            float4 b0 = *(const float4*)&Bs[kk][col0];
            float4 b1 = *(const float4*)&Bs[kk][col0 + 4];
            float av[8] = {a0.x, a0.y, a0.z, a0.w, a1.x, a1.y, a1.z, a1.w};
            float bv[8] = {b0.x, b0.y, b0.z, b0.w, b1.x, b1.y, b1.z, b1.w};
#pragma unroll
            for (int i = 0; i < 8; i++)
#pragma unroll
                for (int j = 0; j < 8; j++) acc[i][j] += av[i] * bv[j];
        }
        __syncthreads();
    }

    // epilogue
#pragma unroll
    for (int i = 0; i < 8; i++) {
        const int m = m0 + row0 + i;
        if (m < M) {
            float* cp = C + (size_t)m * 128 + col0;
#pragma unroll
            for (int j = 0; j < 8; j++) {
                float c = acc[i][j] + bias[col0 + j];
                if (DO_SILU) c = silu_f(c);
                cp[j] = c;
            }
        }
    }
}

// ---------------- small kernels ----------------
__global__ void init_nodes_k(const float* __restrict__ emb,
                             const float* __restrict__ Wn,
                             const float* __restrict__ bn)
{
    int idx = blockIdx.x * blockDim.x + threadIdx.x;
    if (idx < N_NODES * 3) g_coords[idx] = emb[idx];
    if (idx < N_NODES * HDIM) {
        int n = idx >> 7, j = idx & 127;
        float v = emb[n * 3 + 0] * Wn[0 * 128 + j]
                + emb[n * 3 + 1] * Wn[1 * 128 + j]
                + emb[n * 3 + 2] * Wn[2 * 128 + j]
                + bn[j];
        g_V[idx] = v;
    }
}

__global__ void geom_k(const int* __restrict__ srcv, const int* __restrict__ dstv)
{
    int e = blockIdx.x * blockDim.x + threadIdx.x;
    if (e >= N_EDGES) return;
    int s = srcv[e], d = dstv[e];
    float dx = g_coords[d * 3 + 0] - g_coords[s * 3 + 0];
    float dy = g_coords[d * 3 + 1] - g_coords[s * 3 + 1];
    float dz = g_coords[d * 3 + 2] - g_coords[s * 3 + 2];
    g_diff[e * 3 + 0] = dx;
    g_diff[e * 3 + 1] = dy;
    g_diff[e * 3 + 2] = dz;
    g_dist[e] = sqrtf(dx * dx + dy * dy + dz * dz);
}

__global__ void zero_k(float* __restrict__ p, int n)
{
    int idx = blockIdx.x * blockDim.x + threadIdx.x;
    if (idx < n) p[idx] = 0.f;
}

__global__ void scatter_mi_k(const int* __restrict__ dstv)
{
    int idx = blockIdx.x * blockDim.x + threadIdx.x;
    if (idx >= N_EDGES * HDIM) return;
    int e = idx >> 7, j = idx & 127;
    atomicAdd(&g_mi[dstv[e] * HDIM + j], g_mij[idx]);
}

// px = T2 @ Wx2 + bx2 (per edge), then accum[dst] += diff * px
__global__ __launch_bounds__(256) void phix2_k(const float* __restrict__ Wx2,
                                               const float* __restrict__ bx2,
                                               const int* __restrict__ dstv)
{
    __shared__ float w[384];
    __shared__ float bb[3];
    int tid = threadIdx.x;
    for (int i = tid; i < 384; i += 256) w[i] = Wx2[i];
    if (tid < 3) bb[tid] = bx2[tid];
    __syncthreads();

    int gw = blockIdx.x * 8 + (tid >> 5);
    int lane = tid & 31;
    if (gw >= N_EDGES) return;

    const float* row = g_T1 + (size_t)gw * 128;
    float p0 = 0.f, p1 = 0.f, p2 = 0.f;
#pragma unroll
    for (int k = lane; k < 128; k += 32) {
        float t = row[k];
        p0 += t * w[k * 3 + 0];
        p1 += t * w[k * 3 + 1];
        p2 += t * w[k * 3 + 2];
    }
#pragma unroll
    for (int off = 16; off > 0; off >>= 1) {
        p0 += __shfl_xor_sync(0xFFFFFFFF, p0, off);
        p1 += __shfl_xor_sync(0xFFFFFFFF, p1, off);
        p2 += __shfl_xor_sync(0xFFFFFFFF, p2, off);
    }
    if (lane == 0) {
        int d = dstv[gw];
        float px0 = p0 + bb[0], px1 = p1 + bb[1], px2 = p2 + bb[2];
        atomicAdd(&g_accum[d * 3 + 0], g_diff[gw * 3 + 0] * px0);
        atomicAdd(&g_accum[d * 3 + 1], g_diff[gw * 3 + 1] * px1);
        atomicAdd(&g_accum[d * 3 + 2], g_diff[gw * 3 + 2] * px2);
    }
}

__global__ void coords_update_k()
{
    int idx = blockIdx.x * blockDim.x + threadIdx.x;
    if (idx < N_NODES * 3)
        g_coords[idx] += g_accum[idx] * (1.0f / (float)(N_NODES - 1));
}

// ---------------- BatchNorm (deterministic two-stage) ----------------
__global__ void bn_stats1_k(const float* __restrict__ X, int M)
{
    int j = threadIdx.x;           // 128 threads
    int b = blockIdx.x;
    int B = gridDim.x;
    float s = 0.f, q = 0.f;
    for (int r = b; r < M; r += B) {
        float x = elu_f(X[(size_t)r * 128 + j]);
        s += x;
        q += x * x;
    }
    g_part[b * 128 + j] = s;
    g_part[(B + b) * 128 + j] = q;
}

__global__ void bn_stats2_k(int B, int M)
{
    int j = threadIdx.x;           // 128 threads, 1 block
    double s = 0.0, q = 0.0;
    for (int b = 0; b < B; b++) {
        s += (double)g_part[b * 128 + j];
        q += (double)g_part[(B + b) * 128 + j];
    }
    double mu  = s / (double)M;
    double var = q / (double)M - mu * mu;
    g_muinv[j]       = (float)mu;
    g_muinv[128 + j] = (float)rsqrt(var + (double)BN_EPS);
}

__global__ void bn_norm_k(const float* __restrict__ X,
                          const float* __restrict__ gam,
                          const float* __restrict__ bet,
                          float* __restrict__ out, int M)
{
    int idx = blockIdx.x * blockDim.x + threadIdx.x;
    if (idx >= M * 128) return;
    int j = idx & 127;
    float x = elu_f(X[idx]);
    out[idx] = gam[j] * (x - g_muinv[j]) * g_muinv[128 + j] + bet[j];
}

// ---------------- host launcher ----------------
static void* sym_addr(const void* sym)
{
    void* p = nullptr;
    cudaGetSymbolAddress(&p, sym);
    return p;
}

extern "C" void kernel_launch(void* const* d_in, const int* in_sizes, int n_in,
                              void* d_out, int out_size)
{
    (void)in_sizes; (void)n_in; (void)out_size;

    const float* emb_nodes = (const float*)d_in[0];
    const float* emb_edges = (const float*)d_in[1];
    const int*   edge_idx  = (const int*)d_in[2];
    const float* pre_Wn    = (const float*)d_in[3];
    const float* pre_bn    = (const float*)d_in[4];
    // d_in[5], d_in[6] (pre_We/pre_be) are dead: E is overwritten before use
    const float* We1 = (const float*)d_in[7];
    const float* be1 = (const float*)d_in[8];
    const float* We2 = (const float*)d_in[9];
    const float* be2 = (const float*)d_in[10];
    const float* Wx1 = (const float*)d_in[11];
    const float* bx1 = (const float*)d_in[12];
    const float* Wx2 = (const float*)d_in[13];
    const float* bx2 = (const float*)d_in[14];
    const float* Wh1 = (const float*)d_in[15];
    const float* bh1 = (const float*)d_in[16];
    const float* Wh2 = (const float*)d_in[17];
    const float* bh2 = (const float*)d_in[18];
    const float* gam_n = (const float*)d_in[19];
    const float* bet_n = (const float*)d_in[20];
    const float* gam_e = (const float*)d_in[21];
    const float* bet_e = (const float*)d_in[22];

    float* out = (float*)d_out;
    float* outV = out;                      // [N_NODES, 128]
    float* outE = out + (size_t)N_NODES * HDIM; // [N_EDGES, 128]

    const int* srcv = edge_idx;
    const int* dstv = edge_idx + N_EDGES;

    float* pV     = (float*)sym_addr(g_V);
    float* pVraw  = (float*)sym_addr(g_Vraw);
    float* pVH    = (float*)sym_addr(g_VH);
    float* pMi    = (float*)sym_addr(g_mi);
    float* pAccum = (float*)sym_addr(g_accum);
    float* pT1    = (float*)sym_addr(g_T1);
    float* pMij   = (float*)sym_addr(g_mij);
    float* pDist  = (float*)sym_addr(g_dist);

    const int TB = 256;
    const int nodeHBlocks = (N_NODES * HDIM + TB - 1) / TB;
    const int edgeHBlocks = (N_EDGES * HDIM + TB - 1) / TB;
    const int edgeBlocks  = (N_EDGES + TB - 1) / TB;
    const int gemmEdge    = (N_EDGES + 127) / 128;  // 1250
    const int gemmNode    = (N_NODES + 127) / 128;  // 79
    const int BN_B        = 256;

    // init
    init_nodes_k<<<nodeHBlocks, TB>>>(emb_nodes, pre_Wn, pre_bn);

    for (int l = 0; l < NLAYERS; l++) {
        const float* We1l = We1 + (size_t)l * 259 * 128;
        const float* be1l = be1 + l * 128;
        const float* We2l = We2 + (size_t)l * 128 * 128;
        const float* be2l = be2 + l * 128;
        const float* Wx1l = Wx1 + (size_t)l * 128 * 128;
        const float* bx1l = bx1 + l * 128;
        const float* Wx2l = Wx2 + (size_t)l * 128 * 3;
        const float* bx2l = bx2 + l * 3;
        const float* Wh1l = Wh1 + (size_t)l * 256 * 128;
        const float* bh1l = bh1 + l * 128;
        const float* Wh2l = Wh2 + (size_t)l * 128 * 128;
        const float* bh2l = bh2 + l * 128;

        // zero segment-sum accumulators
        zero_k<<<nodeHBlocks, TB>>>(pMi, N_NODES * HDIM);
        zero_k<<<(N_NODES * 3 + TB - 1) / TB, TB>>>(pAccum, N_NODES * 3);

        // geometry: diff, dist
        geom_k<<<edgeBlocks, TB>>>(srcv, dstv);

        // phi_e: T1 = silu(h @ We1 + be1); mij = silu(T1 @ We2 + be2)
        gemm_k<MODE_EDGE, true><<<gemmEdge, 256>>>(
            nullptr, nullptr, We1l, be1l, pT1, N_EDGES, 259,
            srcv, dstv, pV, pDist, emb_edges);
        gemm_k<MODE_PLAIN, true><<<gemmEdge, 256>>>(
            pT1, nullptr, We2l, be2l, pMij, N_EDGES, 128,
            nullptr, nullptr, nullptr, nullptr, nullptr);

        // phi_x: T2 = silu(mij @ Wx1 + bx1) (reuse T1); px + coord scatter
        gemm_k<MODE_PLAIN, true><<<gemmEdge, 256>>>(
            pMij, nullptr, Wx1l, bx1l, pT1, N_EDGES, 128,
            nullptr, nullptr, nullptr, nullptr, nullptr);
        phix2_k<<<(N_EDGES + 7) / 8, 256>>>(Wx2l, bx2l, dstv);

        // mi = segment_sum(mij, dst)
        scatter_mi_k<<<edgeHBlocks, TB>>>(dstv);

        // coords += accum / (N-1)
        coords_update_k<<<(N_NODES * 3 + TB - 1) / TB, TB>>>();

        // phi_h: VH = silu([V, mi] @ Wh1 + bh1); Vraw = VH @ Wh2 + bh2
        gemm_k<MODE_CAT, true><<<gemmNode, 256>>>(
            pV, pMi, Wh1l, bh1l, pVH, N_NODES, 256,
            nullptr, nullptr, nullptr, nullptr, nullptr);
        gemm_k<MODE_PLAIN, false><<<gemmNode, 256>>>(
            pVH, nullptr, Wh2l, bh2l, pVraw, N_NODES, 128,
            nullptr, nullptr, nullptr, nullptr, nullptr);

        // node BN(elu(Vraw)) -> g_V (or d_out V region on last layer)
        bn_stats1_k<<<BN_B, 128>>>(pVraw, N_NODES);
        bn_stats2_k<<<1, 128>>>(BN_B, N_NODES);
        float* vdst = (l == NLAYERS - 1) ? outV : pV;
        bn_norm_k<<<nodeHBlocks, TB>>>(pVraw, gam_n + l * 128, bet_n + l * 128,
                                       vdst, N_NODES);

        // edge BN only matters on the last layer (E overwritten otherwise)
        if (l == NLAYERS - 1) {
            bn_stats1_k<<<BN_B, 128>>>(pMij, N_EDGES);
            bn_stats2_k<<<1, 128>>>(BN_B, N_EDGES);
            bn_norm_k<<<edgeHBlocks, TB>>>(pMij, gam_e + l * 128, bet_e + l * 128,
                                           outE, N_EDGES);
        }
    }
}

// round 2
// speedup vs baseline: 1.2968x; 1.2968x over previous
#include <cuda_runtime.h>
#include <math.h>

typedef unsigned long long ull;

#define N_NODES 10000
#define N_EDGES 160000
#define HDIM    128
#define NLAYERS 3
#define BN_EPS  1e-5f

// ---------------- device scratch ----------------
__device__ float g_coords[N_NODES * 3];
__device__ float g_V[N_NODES * HDIM];
__device__ float g_Vraw[N_NODES * HDIM];
__device__ float g_VH[N_NODES * HDIM];
__device__ float g_mi[N_NODES * HDIM];
__device__ float g_accum[N_NODES * 3];
__device__ float g_mij[N_EDGES * HDIM];
__device__ float g_part[2 * 256 * HDIM];
__device__ float g_muinv[2 * HDIM];

__device__ __forceinline__ float silu_f(float x) { return x / (1.0f + expf(-x)); }
__device__ __forceinline__ float elu_f(float x)  { return x > 0.0f ? x : (expf(x) - 1.0f); }

__device__ __forceinline__ ull fma2(ull a, ull b, ull c) {
    ull d;
    asm("fma.rn.f32x2 %0, %1, %2, %3;" : "=l"(d) : "l"(a), "l"(b), "l"(c));
    return d;
}
__device__ __forceinline__ float2 unpk(ull v) {
    unsigned lo, hi;
    asm("mov.b64 {%0,%1}, %2;" : "=r"(lo), "=r"(hi) : "l"(v));
    return make_float2(__uint_as_float(lo), __uint_as_float(hi));
}

// 128x128 tile FMA2 micro-kernel over one 16-k smem tile.
// A: duplicated-pair layout [16][256] (As2[k][2m]=As2[k][2m+1]=a[m][k])
// B: normal [16][132]
__device__ __forceinline__ void tile_fma(ull (&acc)[8][4], const float* A,
                                         const float* B, int row0, int col0)
{
#pragma unroll
    for (int kk = 0; kk < 16; kk++) {
        const ulonglong2* ap = (const ulonglong2*)(A + kk * 256 + 2 * row0);
        const ulonglong2* bp = (const ulonglong2*)(B + kk * 132 + col0);
        ulonglong2 b01 = bp[0];
        ulonglong2 b23 = bp[1];
        ulonglong2 a0 = ap[0], a1 = ap[1], a2 = ap[2], a3 = ap[3];
        ull av[8] = {a0.x, a0.y, a1.x, a1.y, a2.x, a2.y, a3.x, a3.y};
#pragma unroll
        for (int i = 0; i < 8; i++) {
            acc[i][0] = fma2(av[i], b01.x, acc[i][0]);
            acc[i][1] = fma2(av[i], b01.y, acc[i][1]);
            acc[i][2] = fma2(av[i], b23.x, acc[i][2]);
            acc[i][3] = fma2(av[i], b23.y, acc[i][3]);
        }
    }
}

// ---------------- fused edge pipeline ----------------
// one CTA = 128 edges; computes h -> T1 -> mij (-> atomics to mi, optional
// global mij) -> T2 -> px -> coord atomics, all in shared memory.
__global__ __launch_bounds__(256)
void edge_fused_k(const int* __restrict__ srcv, const int* __restrict__ dstv,
                  const float* __restrict__ ee,
                  const float* __restrict__ We1, const float* __restrict__ be1,
                  const float* __restrict__ We2, const float* __restrict__ be2,
                  const float* __restrict__ Wx1, const float* __restrict__ bx1,
                  const float* __restrict__ Wx2, const float* __restrict__ bx2,
                  int write_mij)
{
    extern __shared__ float smf[];
    float* Ts    = smf;                 // [128][132] tile buffer (T1/mij/T2)
    float* As2   = smf + 16896;         // [2][16][256] A dup-pair, double buf
    float* Bs    = smf + 25088;         // [2][16][132] W tile, double buf
    float* diffs = smf + 29312;         // [128][3]
    float* dists = smf + 29696;         // [128]
    float* wx2s  = smf + 29824;         // [384]
    int*   dsts  = (int*)(smf + 30208); // [128]
    float* bx2s  = smf + 30336;         // [3]

    const int tid  = threadIdx.x;
    const int m0   = blockIdx.x * 128;
    const int arow = tid >> 1;
    const int akb  = (tid & 1) * 8;
    const int brow = tid >> 4;
    const int bcol = (tid & 15) * 8;
    const int row0 = (tid >> 4) * 8;
    const int col0 = (tid & 15) * 8;

    if (tid < 128) {
        int mm = m0 + tid;
        int s = srcv[mm], d = dstv[mm];
        float dx = g_coords[d * 3 + 0] - g_coords[s * 3 + 0];
        float dy = g_coords[d * 3 + 1] - g_coords[s * 3 + 1];
        float dz = g_coords[d * 3 + 2] - g_coords[s * 3 + 2];
        diffs[tid * 3 + 0] = dx;
        diffs[tid * 3 + 1] = dy;
        diffs[tid * 3 + 2] = dz;
        dists[tid] = sqrtf(dx * dx + dy * dy + dz * dz);
        dsts[tid] = d;
    }
    for (int i = tid; i < 384; i += 256) wx2s[i] = Wx2[i];
    if (tid < 3) bx2s[tid] = bx2[tid];

    const int   m   = m0 + arow;
    const int   es  = srcv[m];
    const int   ed  = dstv[m];
    const float ee0 = ee[m * 2 + 0];
    const float ee1 = ee[m * 2 + 1];

    __syncthreads();
    const float edist = dists[arow];

    // gather 8 consecutive h-columns starting at kc (kc multiple of 8;
    // 8-chunks never straddle the 128/256 boundaries)
    auto gatherA8 = [&](int kc, float* v) {
        if (kc < 128) {
            float4 x0 = *(const float4*)(g_V + (size_t)es * 128 + kc);
            float4 x1 = *(const float4*)(g_V + (size_t)es * 128 + kc + 4);
            v[0] = x0.x; v[1] = x0.y; v[2] = x0.z; v[3] = x0.w;
            v[4] = x1.x; v[5] = x1.y; v[6] = x1.z; v[7] = x1.w;
        } else if (kc < 256) {
            float4 x0 = *(const float4*)(g_V + (size_t)ed * 128 + kc - 128);
            float4 x1 = *(const float4*)(g_V + (size_t)ed * 128 + kc - 124);
            v[0] = x0.x; v[1] = x0.y; v[2] = x0.z; v[3] = x0.w;
            v[4] = x1.x; v[5] = x1.y; v[6] = x1.z; v[7] = x1.w;
        } else if (kc == 256) {
            v[0] = edist; v[1] = ee0; v[2] = ee1;
            v[3] = v[4] = v[5] = v[6] = v[7] = 0.f;
        } else {
#pragma unroll
            for (int i = 0; i < 8; i++) v[i] = 0.f;
        }
    };
    auto loadB8 = [&](const float* W, int K, int gk, float* v) {
        if (gk < K) {
            float4 x0 = *(const float4*)(W + (size_t)gk * 128 + bcol);
            float4 x1 = *(const float4*)(W + (size_t)gk * 128 + bcol + 4);
            v[0] = x0.x; v[1] = x0.y; v[2] = x0.z; v[3] = x0.w;
            v[4] = x1.x; v[5] = x1.y; v[6] = x1.z; v[7] = x1.w;
        } else {
#pragma unroll
            for (int i = 0; i < 8; i++) v[i] = 0.f;
        }
    };
    auto storeA = [&](int buf, const float* v) {
        float* base = As2 + buf * 4096;
#pragma unroll
        for (int i = 0; i < 8; i++)
            *(float2*)(base + (akb + i) * 256 + 2 * arow) = make_float2(v[i], v[i]);
    };
    auto storeB = [&](int buf, const float* v) {
        float* base = Bs + buf * 2112 + brow * 132 + bcol;
        *(float4*)(base)     = make_float4(v[0], v[1], v[2], v[3]);
        *(float4*)(base + 4) = make_float4(v[4], v[5], v[6], v[7]);
    };
    auto copyA_Ts = [&](int kb, float* v) {
        const float* p = Ts + arow * 132 + kb + akb;
        float4 x0 = *(const float4*)p;
        float4 x1 = *(const float4*)(p + 4);
        v[0] = x0.x; v[1] = x0.y; v[2] = x0.z; v[3] = x0.w;
        v[4] = x1.x; v[5] = x1.y; v[6] = x1.z; v[7] = x1.w;
    };

    ull acc[8][4];

    // ========== GEMM1: T1 = silu(h @ We1 + be1), K = 259 ==========
#pragma unroll
    for (int i = 0; i < 8; i++)
#pragma unroll
        for (int j = 0; j < 4; j++) acc[i][j] = 0ULL;
    {
        float va[8], vb[8];
        gatherA8(akb, va);              storeA(0, va);
        loadB8(We1, 259, brow, vb);     storeB(0, vb);
    }
    __syncthreads();
    int buf = 0;
    for (int kt = 0; kt < 17; kt++) {
        float va[8], vb[8];
        const bool pre = (kt < 16);
        if (pre) {
            gatherA8((kt + 1) * 16 + akb, va);
            loadB8(We1, 259, (kt + 1) * 16 + brow, vb);
        }
        tile_fma(acc, As2 + buf * 4096, Bs + buf * 2112, row0, col0);
        if (pre) { storeA(buf ^ 1, va); storeB(buf ^ 1, vb); }
        __syncthreads();
        buf ^= 1;
    }
    {
        float b[8];
        *(float4*)b       = *(const float4*)(be1 + col0);
        *(float4*)(b + 4) = *(const float4*)(be1 + col0 + 4);
#pragma unroll
        for (int i = 0; i < 8; i++) {
            float* trow = Ts + (row0 + i) * 132 + col0;
#pragma unroll
            for (int jp = 0; jp < 4; jp++) {
                float2 c = unpk(acc[i][jp]);
                trow[2 * jp]     = silu_f(c.x + b[2 * jp]);
                trow[2 * jp + 1] = silu_f(c.y + b[2 * jp + 1]);
            }
        }
    }
    __syncthreads();

    // ========== GEMM2: mij = silu(T1 @ We2 + be2), K = 128 ==========
#pragma unroll
    for (int i = 0; i < 8; i++)
#pragma unroll
        for (int j = 0; j < 4; j++) acc[i][j] = 0ULL;
    {
        float va[8], vb[8];
        copyA_Ts(0, va);                storeA(0, va);
        loadB8(We2, 128, brow, vb);     storeB(0, vb);
    }
    __syncthreads();
    buf = 0;
    for (int kt = 0; kt < 8; kt++) {
        float va[8], vb[8];
        const bool pre = (kt < 7);
        if (pre) {
            copyA_Ts((kt + 1) * 16, va);
            loadB8(We2, 128, (kt + 1) * 16 + brow, vb);
        }
        tile_fma(acc, As2 + buf * 4096, Bs + buf * 2112, row0, col0);
        if (pre) { storeA(buf ^ 1, va); storeB(buf ^ 1, vb); }
        __syncthreads();
        buf ^= 1;
    }
    {
        float b[8];
        *(float4*)b       = *(const float4*)(be2 + col0);
        *(float4*)(b + 4) = *(const float4*)(be2 + col0 + 4);
#pragma unroll
        for (int i = 0; i < 8; i++) {
            float mv[8];
#pragma unroll
            for (int jp = 0; jp < 4; jp++) {
                float2 c = unpk(acc[i][jp]);
                mv[2 * jp]     = silu_f(c.x + b[2 * jp]);
                mv[2 * jp + 1] = silu_f(c.y + b[2 * jp + 1]);
            }
            const int d = dsts[row0 + i];
#pragma unroll
            for (int j = 0; j < 8; j++)
                atomicAdd(&g_mi[(size_t)d * 128 + col0 + j], mv[j]);
            if (write_mij) {
                float* gp = g_mij + (size_t)(m0 + row0 + i) * 128 + col0;
                *(float4*)gp       = make_float4(mv[0], mv[1], mv[2], mv[3]);
                *(float4*)(gp + 4) = make_float4(mv[4], mv[5], mv[6], mv[7]);
            }
            float* trow = Ts + (row0 + i) * 132 + col0;
#pragma unroll
            for (int j = 0; j < 8; j++) trow[j] = mv[j];
        }
    }
    __syncthreads();

    // ========== GEMM3: T2 = silu(mij @ Wx1 + bx1), K = 128 ==========
#pragma unroll
    for (int i = 0; i < 8; i++)
#pragma unroll
        for (int j = 0; j < 4; j++) acc[i][j] = 0ULL;
    {
        float va[8], vb[8];
        copyA_Ts(0, va);                storeA(0, va);
        loadB8(Wx1, 128, brow, vb);     storeB(0, vb);
    }
    __syncthreads();
    buf = 0;
    for (int kt = 0; kt < 8; kt++) {
        float va[8], vb[8];
        const bool pre = (kt < 7);
        if (pre) {
            copyA_Ts((kt + 1) * 16, va);
            loadB8(Wx1, 128, (kt + 1) * 16 + brow, vb);
        }
        tile_fma(acc, As2 + buf * 4096, Bs + buf * 2112, row0, col0);
        if (pre) { storeA(buf ^ 1, va); storeB(buf ^ 1, vb); }
        __syncthreads();
        buf ^= 1;
    }
    {
        float b[8];
        *(float4*)b       = *(const float4*)(bx1 + col0);
        *(float4*)(b + 4) = *(const float4*)(bx1 + col0 + 4);
#pragma unroll
        for (int i = 0; i < 8; i++) {
            float* trow = Ts + (row0 + i) * 132 + col0;
#pragma unroll
            for (int jp = 0; jp < 4; jp++) {
                float2 c = unpk(acc[i][jp]);
                trow[2 * jp]     = silu_f(c.x + b[2 * jp]);
                trow[2 * jp + 1] = silu_f(c.y + b[2 * jp + 1]);
            }
        }
    }
    __syncthreads();

    // ========== phi_x tail: px = T2 @ Wx2 + bx2; coord scatter ==========
    if (tid < 128) {
        const float* trow = Ts + tid * 132;
        float p0 = 0.f, p1 = 0.f, p2 = 0.f;
#pragma unroll 8
        for (int k = 0; k < 128; k++) {
            float t = trow[k];
            p0 += t * wx2s[k * 3 + 0];
            p1 += t * wx2s[k * 3 + 1];
            p2 += t * wx2s[k * 3 + 2];
        }
        p0 += bx2s[0]; p1 += bx2s[1]; p2 += bx2s[2];
        const int d = dsts[tid];
        atomicAdd(&g_accum[d * 3 + 0], diffs[tid * 3 + 0] * p0);
        atomicAdd(&g_accum[d * 3 + 1], diffs[tid * 3 + 1] * p1);
        atomicAdd(&g_accum[d * 3 + 2], diffs[tid * 3 + 2] * p2);
    }
}

// ---------------- node GEMMs (round-1 kernel, fp32) ----------------
enum { MODE_PLAIN = 0, MODE_CAT = 2 };

template <int MODE, bool DO_SILU>
__global__ __launch_bounds__(256) void gemm_k(
    const float* __restrict__ A, const float* __restrict__ A2,
    const float* __restrict__ W, const float* __restrict__ bias,
    float* __restrict__ C, int M, int K)
{
    __shared__ float As[16][128];
    __shared__ float Bs[16][132];

    const int tid  = threadIdx.x;
    const int m0   = blockIdx.x * 128;
    const int arow = tid >> 1;
    const int akb  = (tid & 1) * 8;
    const int brow = tid >> 4;
    const int bcol = (tid & 15) * 8;
    const int gm   = m0 + arow;
    const bool mval = (gm < M);
    const int row0 = (tid >> 4) * 8;
    const int col0 = (tid & 15) * 8;

    float acc[8][8];
#pragma unroll
    for (int i = 0; i < 8; i++)
#pragma unroll
        for (int j = 0; j < 8; j++) acc[i][j] = 0.f;

    const int nk = (K + 15) >> 4;
    for (int kt = 0; kt < nk; kt++) {
        const int kbase = kt * 16;
        {
            const int gk = kbase + brow;
            if (gk < K) {
                const float* wp = W + (size_t)gk * 128 + bcol;
#pragma unroll
                for (int i = 0; i < 8; i++) Bs[brow][bcol + i] = wp[i];
            } else {
#pragma unroll
                for (int i = 0; i < 8; i++) Bs[brow][bcol + i] = 0.f;
            }
        }
        if (MODE == MODE_PLAIN) {
#pragma unroll
            for (int i = 0; i < 8; i++) {
                const int gk = kbase + akb + i;
                As[akb + i][arow] = (mval && gk < K) ? A[(size_t)gm * K + gk] : 0.f;
            }
        } else {
#pragma unroll
            for (int i = 0; i < 8; i++) {
                const int gk = kbase + akb + i;
                float v = 0.f;
                if (mval) {
                    v = (gk < 128) ? A[(size_t)gm * 128 + gk]
                                   : A2[(size_t)gm * 128 + (gk - 128)];
                }
                As[akb + i][arow] = v;
            }
        }
        __syncthreads();
#pragma unroll
        for (int kk = 0; kk < 16; kk++) {
            float4 a0 = *(const float4*)&As[kk][row0];
            float4 a1 = *(const float4*)&As[kk][row0 + 4];
            float4 b0 = *(const float4*)&Bs[kk][col0];
            float4 b1 = *(const float4*)&Bs[kk][col0 + 4];
            float av[8] = {a0.x, a0.y, a0.z, a0.w, a1.x, a1.y, a1.z, a1.w};
            float bv[8] = {b0.x, b0.y, b0.z, b0.w, b1.x, b1.y, b1.z, b1.w};
#pragma unroll
            for (int i = 0; i < 8; i++)
#pragma unroll
                for (int j = 0; j < 8; j++) acc[i][j] += av[i] * bv[j];
        }
        __syncthreads();
    }
#pragma unroll
    for (int i = 0; i < 8; i++) {
        const int mm = m0 + row0 + i;
        if (mm < M) {
            float* cp = C + (size_t)mm * 128 + col0;
#pragma unroll
            for (int j = 0; j < 8; j++) {
                float c = acc[i][j] + bias[col0 + j];
                if (DO_SILU) c = silu_f(c);
                cp[j] = c;
            }
        }
    }
}

// ---------------- small kernels ----------------
__global__ void init_nodes_k(const float* __restrict__ emb,
                             const float* __restrict__ Wn,
                             const float* __restrict__ bn)
{
    int idx = blockIdx.x * blockDim.x + threadIdx.x;
    if (idx < N_NODES * 3) g_coords[idx] = emb[idx];
    if (idx < N_NODES * HDIM) {
        int n = idx >> 7, j = idx & 127;
        g_V[idx] = emb[n * 3 + 0] * Wn[0 * 128 + j]
                 + emb[n * 3 + 1] * Wn[1 * 128 + j]
                 + emb[n * 3 + 2] * Wn[2 * 128 + j]
                 + bn[j];
    }
}

__global__ void zero_k(float* __restrict__ p, int n)
{
    int idx = blockIdx.x * blockDim.x + threadIdx.x;
    if (idx < n) p[idx] = 0.f;
}

__global__ void coords_update_k()
{
    int idx = blockIdx.x * blockDim.x + threadIdx.x;
    if (idx < N_NODES * 3)
        g_coords[idx] += g_accum[idx] * (1.0f / (float)(N_NODES - 1));
}

// ---------------- BatchNorm (deterministic two-stage) ----------------
__global__ void bn_stats1_k(const float* __restrict__ X, int M)
{
    int j = threadIdx.x;
    int b = blockIdx.x;
    int B = gridDim.x;
    float s = 0.f, q = 0.f;
    for (int r = b; r < M; r += B) {
        float x = elu_f(X[(size_t)r * 128 + j]);
        s += x;
        q += x * x;
    }
    g_part[b * 128 + j] = s;
    g_part[(B + b) * 128 + j] = q;
}

__global__ void bn_stats2_k(int B, int M)
{
    int j = threadIdx.x;
    double s = 0.0, q = 0.0;
    for (int b = 0; b < B; b++) {
        s += (double)g_part[b * 128 + j];
        q += (double)g_part[(B + b) * 128 + j];
    }
    double mu  = s / (double)M;
    double var = q / (double)M - mu * mu;
    g_muinv[j]       = (float)mu;
    g_muinv[128 + j] = (float)rsqrt(var + (double)BN_EPS);
}

__global__ void bn_norm_k(const float* __restrict__ X,
                          const float* __restrict__ gam,
                          const float* __restrict__ bet,
                          float* __restrict__ out, int M)
{
    int idx = blockIdx.x * blockDim.x + threadIdx.x;
    if (idx >= M * 128) return;
    int j = idx & 127;
    float x = elu_f(X[idx]);
    out[idx] = gam[j] * (x - g_muinv[j]) * g_muinv[128 + j] + bet[j];
}

// ---------------- host launcher ----------------
static void* sym_addr(const void* sym)
{
    void* p = nullptr;
    cudaGetSymbolAddress(&p, sym);
    return p;
}

extern "C" void kernel_launch(void* const* d_in, const int* in_sizes, int n_in,
                              void* d_out, int out_size)
{
    (void)in_sizes; (void)n_in; (void)out_size;

    const float* emb_nodes = (const float*)d_in[0];
    const float* emb_edges = (const float*)d_in[1];
    const int*   edge_idx  = (const int*)d_in[2];
    const float* pre_Wn    = (const float*)d_in[3];
    const float* pre_bn    = (const float*)d_in[4];
    const float* We1 = (const float*)d_in[7];
    const float* be1 = (const float*)d_in[8];
    const float* We2 = (const float*)d_in[9];
    const float* be2 = (const float*)d_in[10];
    const float* Wx1 = (const float*)d_in[11];
    const float* bx1 = (const float*)d_in[12];
    const float* Wx2 = (const float*)d_in[13];
    const float* bx2 = (const float*)d_in[14];
    const float* Wh1 = (const float*)d_in[15];
    const float* bh1 = (const float*)d_in[16];
    const float* Wh2 = (const float*)d_in[17];
    const float* bh2 = (const float*)d_in[18];
    const float* gam_n = (const float*)d_in[19];
    const float* bet_n = (const float*)d_in[20];
    const float* gam_e = (const float*)d_in[21];
    const float* bet_e = (const float*)d_in[22];

    float* out  = (float*)d_out;
    float* outV = out;
    float* outE = out + (size_t)N_NODES * HDIM;

    const int* srcv = edge_idx;
    const int* dstv = edge_idx + N_EDGES;

    float* pV    = (float*)sym_addr(g_V);
    float* pVraw = (float*)sym_addr(g_Vraw);
    float* pVH   = (float*)sym_addr(g_VH);
    float* pMi   = (float*)sym_addr(g_mi);
    float* pAcc  = (float*)sym_addr(g_accum);
    float* pMij  = (float*)sym_addr(g_mij);

    const int EDGE_SMEM = 30340 * 4;  // 121360 B dynamic smem
    cudaFuncSetAttribute(edge_fused_k,
                         cudaFuncAttributeMaxDynamicSharedMemorySize, EDGE_SMEM);

    const int TB = 256;
    const int nodeHBlocks = (N_NODES * HDIM + TB - 1) / TB;
    const int edgeHBlocks = (N_EDGES * HDIM + TB - 1) / TB;
    const int gemmNode    = (N_NODES + 127) / 128;
    const int edgeTiles   = N_EDGES / 128;  // 1250, exact
    const int BN_B        = 256;

    init_nodes_k<<<nodeHBlocks, TB>>>(emb_nodes, pre_Wn, pre_bn);

    for (int l = 0; l < NLAYERS; l++) {
        const float* We1l = We1 + (size_t)l * 259 * 128;
        const float* be1l = be1 + l * 128;
        const float* We2l = We2 + (size_t)l * 128 * 128;
        const float* be2l = be2 + l * 128;
        const float* Wx1l = Wx1 + (size_t)l * 128 * 128;
        const float* bx1l = bx1 + l * 128;
        const float* Wx2l = Wx2 + (size_t)l * 128 * 3;
        const float* bx2l = bx2 + l * 3;
        const float* Wh1l = Wh1 + (size_t)l * 256 * 128;
        const float* bh1l = bh1 + l * 128;
        const float* Wh2l = Wh2 + (size_t)l * 128 * 128;
        const float* bh2l = bh2 + l * 128;

        zero_k<<<nodeHBlocks, TB>>>(pMi, N_NODES * HDIM);
        zero_k<<<(N_NODES * 3 + TB - 1) / TB, TB>>>(pAcc, N_NODES * 3);

        edge_fused_k<<<edgeTiles, 256, EDGE_SMEM>>>(
            srcv, dstv, emb_edges,
            We1l, be1l, We2l, be2l, Wx1l, bx1l, Wx2l, bx2l,
            (l == NLAYERS - 1) ? 1 : 0);

        coords_update_k<<<(N_NODES * 3 + TB - 1) / TB, TB>>>();

        gemm_k<MODE_CAT, true><<<gemmNode, 256>>>(
            pV, pMi, Wh1l, bh1l, pVH, N_NODES, 256);
        gemm_k<MODE_PLAIN, false><<<gemmNode, 256>>>(
            pVH, nullptr, Wh2l, bh2l, pVraw, N_NODES, 128);

        bn_stats1_k<<<BN_B, 128>>>(pVraw, N_NODES);
        bn_stats2_k<<<1, 128>>>(BN_B, N_NODES);
        float* vdst = (l == NLAYERS - 1) ? outV : pV;
        bn_norm_k<<<nodeHBlocks, TB>>>(pVraw, gam_n + l * 128, bet_n + l * 128,
                                       vdst, N_NODES);

        if (l == NLAYERS - 1) {
            bn_stats1_k<<<BN_B, 128>>>(pMij, N_EDGES);
            bn_stats2_k<<<1, 128>>>(BN_B, N_EDGES);
            bn_norm_k<<<edgeHBlocks, TB>>>(pMij, gam_e + l * 128, bet_e + l * 128,
                                           outE, N_EDGES);
        }
    }
}

// round 3
// speedup vs baseline: 1.9306x; 1.4887x over previous
#include <cuda_runtime.h>
#include <math.h>

typedef unsigned long long ull;

#define N_NODES 10000
#define N_EDGES 160000
#define HDIM    128
#define NLAYERS 3
#define BN_EPS  1e-5f

// ---------------- device scratch ----------------
__device__ float g_coords[N_NODES * 3];
__device__ float g_V[N_NODES * HDIM];
__device__ float g_Vraw[N_NODES * HDIM];   // reused as Pd during edge phase
__device__ float g_VH[N_NODES * HDIM];     // reused as Ps during edge phase
__device__ float g_mi[N_NODES * HDIM];
__device__ float g_accum[N_NODES * 3];
__device__ float g_mij[N_EDGES * HDIM];
__device__ float g_part[2 * 256 * HDIM];
__device__ float g_muinv[2 * HDIM];

__device__ __forceinline__ float silu_f(float x) { return x / (1.0f + expf(-x)); }
__device__ __forceinline__ float elu_f(float x)  { return x > 0.0f ? x : (expf(x) - 1.0f); }

__device__ __forceinline__ ull fma2(ull a, ull b, ull c) {
    ull d;
    asm("fma.rn.f32x2 %0, %1, %2, %3;" : "=l"(d) : "l"(a), "l"(b), "l"(c));
    return d;
}
__device__ __forceinline__ float2 unpk(ull v) {
    unsigned lo, hi;
    asm("mov.b64 {%0,%1}, %2;" : "=r"(lo), "=r"(hi) : "l"(v));
    return make_float2(__uint_as_float(lo), __uint_as_float(hi));
}
__device__ __forceinline__ ull dup2(float a) {
    ull d;
    asm("mov.b64 %0, {%1,%1};" : "=l"(d) : "f"(a));
    return d;
}

// Ts tile addressing: row stride 132 floats + 16B row-group swizzle so that
// rows 8 apart land on different banks (scalar A-column reads conflict-free).
__device__ __forceinline__ int ts_off(int r, int c) {
    return r * 132 + ((r >> 3) & 1) * 4 + c;
}

// micro-GEMM over one 16-k slab: acc[8 rows][4 col-pairs] += Ts-col-slice * Bs
__device__ __forceinline__ void gemm_tile(ull (&acc)[8][4], const float* Ts,
                                          const float* Bs, int kbase,
                                          int row0, int col0)
{
    const float* arow = Ts + row0 * 132 + ((row0 >> 3) & 1) * 4 + kbase;
#pragma unroll
    for (int kk = 0; kk < 16; kk++) {
        const float* bp = Bs + kk * 132 + col0;
        ulonglong2 b01 = *(const ulonglong2*)bp;
        ulonglong2 b23 = *(const ulonglong2*)(bp + 4);
#pragma unroll
        for (int i = 0; i < 8; i++) {
            ull av = dup2(arow[i * 132 + kk]);
            acc[i][0] = fma2(av, b01.x, acc[i][0]);
            acc[i][1] = fma2(av, b01.y, acc[i][1]);
            acc[i][2] = fma2(av, b23.x, acc[i][2]);
            acc[i][3] = fma2(av, b23.y, acc[i][3]);
        }
    }
}

// ---------------- fused edge pipeline (per layer) ----------------
// CTA = 128 edges. T1 built by gather-add of node-level projections Ps/Pd,
// then two 128x128x128 GEMMs (We2, Wx1) in shared memory, then px + scatters.
__global__ __launch_bounds__(256, 2)
void edge_fused_k(const int* __restrict__ srcv, const int* __restrict__ dstv,
                  const float* __restrict__ ee,
                  const float* __restrict__ Ps, const float* __restrict__ Pd,
                  const float* __restrict__ We1_tail,  // rows 256..258 of We1
                  const float* __restrict__ be1,
                  const float* __restrict__ We2, const float* __restrict__ be2,
                  const float* __restrict__ Wx1, const float* __restrict__ bx1,
                  const float* __restrict__ Wx2, const float* __restrict__ bx2,
                  int write_mij)
{
    extern __shared__ float smf[];
    float* Ts    = smf;                   // 16896 : [128][132+swz] tile
    float* Bs    = smf + 16896;           // 4224  : [2][16][132] weight tiles
    float* wex   = smf + 21120;           // 384   : We1 rows 256..258
    float* be1s  = smf + 21504;           // 128
    float* wx2s  = smf + 21632;           // 384
    float* bx2s  = smf + 22016;           // 4
    float* diffs = smf + 22020;           // 384
    float* dists = smf + 22404;           // 128
    float* ee0s  = smf + 22532;           // 128
    float* ee1s  = smf + 22660;           // 128
    int*   dsts  = (int*)(smf + 22788);   // 128

    const int tid  = threadIdx.x;
    const int m0   = blockIdx.x * 128;
    const int brow = tid >> 4;            // B-load: k row 0..15
    const int bcol = (tid & 15) * 8;      // B-load: col
    const int row0 = (tid >> 4) * 8;      // compute tile
    const int col0 = (tid & 15) * 8;

    // ---- phase 0: per-edge geometry + small weights to smem ----
    if (tid < 128) {
        int mm = m0 + tid;
        int s = srcv[mm], d = dstv[mm];
        float dx = g_coords[d * 3 + 0] - g_coords[s * 3 + 0];
        float dy = g_coords[d * 3 + 1] - g_coords[s * 3 + 1];
        float dz = g_coords[d * 3 + 2] - g_coords[s * 3 + 2];
        diffs[tid * 3 + 0] = dx;
        diffs[tid * 3 + 1] = dy;
        diffs[tid * 3 + 2] = dz;
        dists[tid] = sqrtf(dx * dx + dy * dy + dz * dz);
        dsts[tid] = d;
        ee0s[tid] = ee[mm * 2 + 0];
        ee1s[tid] = ee[mm * 2 + 1];
    }
    for (int i = tid; i < 384; i += 256) { wex[i] = We1_tail[i]; wx2s[i] = Wx2[i]; }
    if (tid < 128) be1s[tid] = be1[tid];
    if (tid < 3)   bx2s[tid] = bx2[tid];
    __syncthreads();

    // ---- phase 1: T1 = silu(Ps[src] + Pd[dst] + dist*w256 + ee@W + be1) ----
    {
        const int r  = tid >> 1;
        const int mm = m0 + r;
        const int s  = srcv[mm];
        const int d  = dstv[mm];
        const float di = dists[r], e0 = ee0s[r], e1 = ee1s[r];
        const int cb = (tid & 1) * 64;
        const float* psp = Ps + (size_t)s * 128;
        const float* pdp = Pd + (size_t)d * 128;
#pragma unroll 4
        for (int c = cb; c < cb + 64; c += 4) {
            float4 a = *(const float4*)(psp + c);
            float4 b = *(const float4*)(pdp + c);
            float4 o;
            o.x = silu_f(a.x + b.x + di * wex[c+0] + e0 * wex[128+c+0] + e1 * wex[256+c+0] + be1s[c+0]);
            o.y = silu_f(a.y + b.y + di * wex[c+1] + e0 * wex[128+c+1] + e1 * wex[256+c+1] + be1s[c+1]);
            o.z = silu_f(a.z + b.z + di * wex[c+2] + e0 * wex[128+c+2] + e1 * wex[256+c+2] + be1s[c+2]);
            o.w = silu_f(a.w + b.w + di * wex[c+3] + e0 * wex[128+c+3] + e1 * wex[256+c+3] + be1s[c+3]);
            *(float4*)(Ts + ts_off(r, c)) = o;
        }
    }
    __syncthreads();

    auto loadB8 = [&](const float* W, int gk, float* v) {
        float4 x0 = *(const float4*)(W + (size_t)gk * 128 + bcol);
        float4 x1 = *(const float4*)(W + (size_t)gk * 128 + bcol + 4);
        v[0] = x0.x; v[1] = x0.y; v[2] = x0.z; v[3] = x0.w;
        v[4] = x1.x; v[5] = x1.y; v[6] = x1.z; v[7] = x1.w;
    };
    auto storeB = [&](int buf, const float* v) {
        float* base = Bs + buf * 2112 + brow * 132 + bcol;
        *(float4*)(base)     = make_float4(v[0], v[1], v[2], v[3]);
        *(float4*)(base + 4) = make_float4(v[4], v[5], v[6], v[7]);
    };

    ull acc[8][4];

    // ---- phase 2: mij = silu(T1 @ We2 + be2) ----
#pragma unroll
    for (int i = 0; i < 8; i++)
#pragma unroll
        for (int j = 0; j < 4; j++) acc[i][j] = 0ULL;
    {
        float vb[8];
        loadB8(We2, brow, vb); storeB(0, vb);
    }
    __syncthreads();
    int buf = 0;
    for (int kt = 0; kt < 8; kt++) {
        float nb[8];
        const bool pre = (kt < 7);
        if (pre) loadB8(We2, (kt + 1) * 16 + brow, nb);
        gemm_tile(acc, Ts, Bs + buf * 2112, kt * 16, row0, col0);
        if (pre) storeB(buf ^ 1, nb);
        __syncthreads();
        buf ^= 1;
    }
    {
        float b[8];
        *(float4*)b       = *(const float4*)(be2 + col0);
        *(float4*)(b + 4) = *(const float4*)(be2 + col0 + 4);
#pragma unroll
        for (int i = 0; i < 8; i++) {
            float mv[8];
#pragma unroll
            for (int jp = 0; jp < 4; jp++) {
                float2 c = unpk(acc[i][jp]);
                mv[2 * jp]     = silu_f(c.x + b[2 * jp]);
                mv[2 * jp + 1] = silu_f(c.y + b[2 * jp + 1]);
            }
            const int d = dsts[row0 + i];
#pragma unroll
            for (int j = 0; j < 8; j++)
                atomicAdd(&g_mi[(size_t)d * 128 + col0 + j], mv[j]);
            if (write_mij) {
                float* gp = g_mij + (size_t)(m0 + row0 + i) * 128 + col0;
                *(float4*)gp       = make_float4(mv[0], mv[1], mv[2], mv[3]);
                *(float4*)(gp + 4) = make_float4(mv[4], mv[5], mv[6], mv[7]);
            }
            float* trow = Ts + ts_off(row0 + i, col0);
            *(float4*)trow       = make_float4(mv[0], mv[1], mv[2], mv[3]);
            *(float4*)(trow + 4) = make_float4(mv[4], mv[5], mv[6], mv[7]);
        }
    }
    __syncthreads();

    // ---- phase 3: T2 = silu(mij @ Wx1 + bx1) ----
#pragma unroll
    for (int i = 0; i < 8; i++)
#pragma unroll
        for (int j = 0; j < 4; j++) acc[i][j] = 0ULL;
    {
        float vb[8];
        loadB8(Wx1, brow, vb); storeB(0, vb);
    }
    __syncthreads();
    buf = 0;
    for (int kt = 0; kt < 8; kt++) {
        float nb[8];
        const bool pre = (kt < 7);
        if (pre) loadB8(Wx1, (kt + 1) * 16 + brow, nb);
        gemm_tile(acc, Ts, Bs + buf * 2112, kt * 16, row0, col0);
        if (pre) storeB(buf ^ 1, nb);
        __syncthreads();
        buf ^= 1;
    }
    {
        float b[8];
        *(float4*)b       = *(const float4*)(bx1 + col0);
        *(float4*)(b + 4) = *(const float4*)(bx1 + col0 + 4);
#pragma unroll
        for (int i = 0; i < 8; i++) {
            float* trow = Ts + ts_off(row0 + i, col0);
#pragma unroll
            for (int jp = 0; jp < 4; jp++) {
                float2 c = unpk(acc[i][jp]);
                trow[2 * jp]     = silu_f(c.x + b[2 * jp]);
                trow[2 * jp + 1] = silu_f(c.y + b[2 * jp + 1]);
            }
        }
    }
    __syncthreads();

    // ---- phase 4: px = T2 @ Wx2 + bx2 ; coord scatter ----
    if (tid < 128) {
        const float* trow = Ts + ts_off(tid, 0);
        float p0 = 0.f, p1 = 0.f, p2 = 0.f;
#pragma unroll 8
        for (int k = 0; k < 128; k++) {
            float t = trow[k];
            p0 += t * wx2s[k * 3 + 0];
            p1 += t * wx2s[k * 3 + 1];
            p2 += t * wx2s[k * 3 + 2];
        }
        p0 += bx2s[0]; p1 += bx2s[1]; p2 += bx2s[2];
        const int d = dsts[tid];
        atomicAdd(&g_accum[d * 3 + 0], diffs[tid * 3 + 0] * p0);
        atomicAdd(&g_accum[d * 3 + 1], diffs[tid * 3 + 1] * p1);
        atomicAdd(&g_accum[d * 3 + 2], diffs[tid * 3 + 2] * p2);
    }
}

// ---------------- node GEMMs ----------------
enum { MODE_PLAIN = 0, MODE_CAT = 2 };

template <int MODE, bool DO_SILU, bool HAS_BIAS>
__global__ __launch_bounds__(256) void gemm_k(
    const float* __restrict__ A, const float* __restrict__ A2,
    const float* __restrict__ W, const float* __restrict__ bias,
    float* __restrict__ C, int M, int K)
{
    __shared__ float As[16][128];
    __shared__ float Bs[16][132];

    const int tid  = threadIdx.x;
    const int m0   = blockIdx.x * 128;
    const int arow = tid >> 1;
    const int akb  = (tid & 1) * 8;
    const int brow = tid >> 4;
    const int bcol = (tid & 15) * 8;
    const int gm   = m0 + arow;
    const bool mval = (gm < M);
    const int row0 = (tid >> 4) * 8;
    const int col0 = (tid & 15) * 8;

    float acc[8][8];
#pragma unroll
    for (int i = 0; i < 8; i++)
#pragma unroll
        for (int j = 0; j < 8; j++) acc[i][j] = 0.f;

    const int nk = (K + 15) >> 4;
    for (int kt = 0; kt < nk; kt++) {
        const int kbase = kt * 16;
        {
            const int gk = kbase + brow;
            if (gk < K) {
                const float* wp = W + (size_t)gk * 128 + bcol;
#pragma unroll
                for (int i = 0; i < 8; i++) Bs[brow][bcol + i] = wp[i];
            } else {
#pragma unroll
                for (int i = 0; i < 8; i++) Bs[brow][bcol + i] = 0.f;
            }
        }
        if (MODE == MODE_PLAIN) {
#pragma unroll
            for (int i = 0; i < 8; i++) {
                const int gk = kbase + akb + i;
                As[akb + i][arow] = (mval && gk < K) ? A[(size_t)gm * K + gk] : 0.f;
            }
        } else {
#pragma unroll
            for (int i = 0; i < 8; i++) {
                const int gk = kbase + akb + i;
                float v = 0.f;
                if (mval) {
                    v = (gk < 128) ? A[(size_t)gm * 128 + gk]
                                   : A2[(size_t)gm * 128 + (gk - 128)];
                }
                As[akb + i][arow] = v;
            }
        }
        __syncthreads();
#pragma unroll
        for (int kk = 0; kk < 16; kk++) {
            float4 a0 = *(const float4*)&As[kk][row0];
            float4 a1 = *(const float4*)&As[kk][row0 + 4];
            float4 b0 = *(const float4*)&Bs[kk][col0];
            float4 b1 = *(const float4*)&Bs[kk][col0 + 4];
            float av[8] = {a0.x, a0.y, a0.z, a0.w, a1.x, a1.y, a1.z, a1.w};
            float bv[8] = {b0.x, b0.y, b0.z, b0.w, b1.x, b1.y, b1.z, b1.w};
#pragma unroll
            for (int i = 0; i < 8; i++)
#pragma unroll
                for (int j = 0; j < 8; j++) acc[i][j] += av[i] * bv[j];
        }
        __syncthreads();
    }
#pragma unroll
    for (int i = 0; i < 8; i++) {
        const int mm = m0 + row0 + i;
        if (mm < M) {
            float* cp = C + (size_t)mm * 128 + col0;
#pragma unroll
            for (int j = 0; j < 8; j++) {
                float c = acc[i][j] + (HAS_BIAS ? bias[col0 + j] : 0.f);
                if (DO_SILU) c = silu_f(c);
                cp[j] = c;
            }
        }
    }
}

// ---------------- small kernels ----------------
__global__ void init_nodes_k(const float* __restrict__ emb,
                             const float* __restrict__ Wn,
                             const float* __restrict__ bn)
{
    int idx = blockIdx.x * blockDim.x + threadIdx.x;
    if (idx < N_NODES * 3) g_coords[idx] = emb[idx];
    if (idx < N_NODES * HDIM) {
        int n = idx >> 7, j = idx & 127;
        g_V[idx] = emb[n * 3 + 0] * Wn[0 * 128 + j]
                 + emb[n * 3 + 1] * Wn[1 * 128 + j]
                 + emb[n * 3 + 2] * Wn[2 * 128 + j]
                 + bn[j];
    }
}

__global__ void zero_k(float* __restrict__ p, int n)
{
    int idx = blockIdx.x * blockDim.x + threadIdx.x;
    if (idx < n) p[idx] = 0.f;
}

__global__ void coords_update_k()
{
    int idx = blockIdx.x * blockDim.x + threadIdx.x;
    if (idx < N_NODES * 3)
        g_coords[idx] += g_accum[idx] * (1.0f / (float)(N_NODES - 1));
}

// ---------------- BatchNorm (deterministic two-stage) ----------------
__global__ void bn_stats1_k(const float* __restrict__ X, int M)
{
    int j = threadIdx.x;
    int b = blockIdx.x;
    int B = gridDim.x;
    float s = 0.f, q = 0.f;
    for (int r = b; r < M; r += B) {
        float x = elu_f(X[(size_t)r * 128 + j]);
        s += x;
        q += x * x;
    }
    g_part[b * 128 + j] = s;
    g_part[(B + b) * 128 + j] = q;
}

__global__ void bn_stats2_k(int B, int M)
{
    int j = threadIdx.x;
    double s = 0.0, q = 0.0;
    for (int b = 0; b < B; b++) {
        s += (double)g_part[b * 128 + j];
        q += (double)g_part[(B + b) * 128 + j];
    }
    double mu  = s / (double)M;
    double var = q / (double)M - mu * mu;
    g_muinv[j]       = (float)mu;
    g_muinv[128 + j] = (float)rsqrt(var + (double)BN_EPS);
}

__global__ void bn_norm_k(const float* __restrict__ X,
                          const float* __restrict__ gam,
                          const float* __restrict__ bet,
                          float* __restrict__ out, int M)
{
    int idx = blockIdx.x * blockDim.x + threadIdx.x;
    if (idx >= M * 128) return;
    int j = idx & 127;
    float x = elu_f(X[idx]);
    out[idx] = gam[j] * (x - g_muinv[j]) * g_muinv[128 + j] + bet[j];
}

// ---------------- host launcher ----------------
static void* sym_addr(const void* sym)
{
    void* p = nullptr;
    cudaGetSymbolAddress(&p, sym);
    return p;
}

extern "C" void kernel_launch(void* const* d_in, const int* in_sizes, int n_in,
                              void* d_out, int out_size)
{
    (void)in_sizes; (void)n_in; (void)out_size;

    const float* emb_nodes = (const float*)d_in[0];
    const float* emb_edges = (const float*)d_in[1];
    const int*   edge_idx  = (const int*)d_in[2];
    const float* pre_Wn    = (const float*)d_in[3];
    const float* pre_bn    = (const float*)d_in[4];
    const float* We1 = (const float*)d_in[7];
    const float* be1 = (const float*)d_in[8];
    const float* We2 = (const float*)d_in[9];
    const float* be2 = (const float*)d_in[10];
    const float* Wx1 = (const float*)d_in[11];
    const float* bx1 = (const float*)d_in[12];
    const float* Wx2 = (const float*)d_in[13];
    const float* bx2 = (const float*)d_in[14];
    const float* Wh1 = (const float*)d_in[15];
    const float* bh1 = (const float*)d_in[16];
    const float* Wh2 = (const float*)d_in[17];
    const float* bh2 = (const float*)d_in[18];
    const float* gam_n = (const float*)d_in[19];
    const float* bet_n = (const float*)d_in[20];
    const float* gam_e = (const float*)d_in[21];
    const float* bet_e = (const float*)d_in[22];

    float* out  = (float*)d_out;
    float* outV = out;
    float* outE = out + (size_t)N_NODES * HDIM;

    const int* srcv = edge_idx;
    const int* dstv = edge_idx + N_EDGES;

    float* pV    = (float*)sym_addr(g_V);
    float* pVraw = (float*)sym_addr(g_Vraw);
    float* pVH   = (float*)sym_addr(g_VH);
    float* pMi   = (float*)sym_addr(g_mi);
    float* pAcc  = (float*)sym_addr(g_accum);
    float* pMij  = (float*)sym_addr(g_mij);

    const int EDGE_SMEM = 22916 * 4;  // 91664 B
    cudaFuncSetAttribute(edge_fused_k,
                         cudaFuncAttributeMaxDynamicSharedMemorySize, EDGE_SMEM);

    const int TB = 256;
    const int nodeHBlocks = (N_NODES * HDIM + TB - 1) / TB;
    const int edgeHBlocks = (N_EDGES * HDIM + TB - 1) / TB;
    const int gemmNode    = (N_NODES + 127) / 128;
    const int edgeTiles   = N_EDGES / 128;  // 1250, exact
    const int BN_B        = 256;

    init_nodes_k<<<nodeHBlocks, TB>>>(emb_nodes, pre_Wn, pre_bn);

    for (int l = 0; l < NLAYERS; l++) {
        const float* We1l = We1 + (size_t)l * 259 * 128;
        const float* be1l = be1 + l * 128;
        const float* We2l = We2 + (size_t)l * 128 * 128;
        const float* be2l = be2 + l * 128;
        const float* Wx1l = Wx1 + (size_t)l * 128 * 128;
        const float* bx1l = bx1 + l * 128;
        const float* Wx2l = Wx2 + (size_t)l * 128 * 3;
        const float* bx2l = bx2 + l * 3;
        const float* Wh1l = Wh1 + (size_t)l * 256 * 128;
        const float* bh1l = bh1 + l * 128;
        const float* Wh2l = Wh2 + (size_t)l * 128 * 128;
        const float* bh2l = bh2 + l * 128;

        zero_k<<<nodeHBlocks, TB>>>(pMi, N_NODES * HDIM);
        zero_k<<<(N_NODES * 3 + TB - 1) / TB, TB>>>(pAcc, N_NODES * 3);

        // node-level projections: Ps = V @ We1[0:128] -> g_VH,
        //                         Pd = V @ We1[128:256] -> g_Vraw
        gemm_k<MODE_PLAIN, false, false><<<gemmNode, 256>>>(
            pV, nullptr, We1l, nullptr, pVH, N_NODES, 128);
        gemm_k<MODE_PLAIN, false, false><<<gemmNode, 256>>>(
            pV, nullptr, We1l + 128 * 128, nullptr, pVraw, N_NODES, 128);

        edge_fused_k<<<edgeTiles, 256, EDGE_SMEM>>>(
            srcv, dstv, emb_edges, pVH, pVraw,
            We1l + 256 * 128, be1l,
            We2l, be2l, Wx1l, bx1l, Wx2l, bx2l,
            (l == NLAYERS - 1) ? 1 : 0);

        coords_update_k<<<(N_NODES * 3 + TB - 1) / TB, TB>>>();

        gemm_k<MODE_CAT, true, true><<<gemmNode, 256>>>(
            pV, pMi, Wh1l, bh1l, pVH, N_NODES, 256);
        gemm_k<MODE_PLAIN, false, true><<<gemmNode, 256>>>(
            pVH, nullptr, Wh2l, bh2l, pVraw, N_NODES, 128);

        bn_stats1_k<<<BN_B, 128>>>(pVraw, N_NODES);
        bn_stats2_k<<<1, 128>>>(BN_B, N_NODES);
        float* vdst = (l == NLAYERS - 1) ? outV : pV;
        bn_norm_k<<<nodeHBlocks, TB>>>(pVraw, gam_n + l * 128, bet_n + l * 128,
                                       vdst, N_NODES);

        if (l == NLAYERS - 1) {
            bn_stats1_k<<<BN_B, 128>>>(pMij, N_EDGES);
            bn_stats2_k<<<1, 128>>>(BN_B, N_EDGES);
            bn_norm_k<<<edgeHBlocks, TB>>>(pMij, gam_e + l * 128, bet_e + l * 128,
                                           outE, N_EDGES);
        }
    }
}

// round 4
// speedup vs baseline: 2.0296x; 1.0513x over previous
#include <cuda_runtime.h>
#include <math.h>

typedef unsigned long long ull;

#define N_NODES 10000
#define N_EDGES 160000
#define HDIM    128
#define NLAYERS 3
#define BN_EPS  1e-5f

#define EDGE_TILES (N_EDGES / 128)   // 1250
#define NODE_TILES ((N_NODES + 63) / 64)  // 157

// ---------------- device scratch ----------------
__device__ float g_coords[N_NODES * 3];
__device__ float g_V[N_NODES * HDIM];
__device__ float g_Vraw[N_NODES * HDIM];   // reused as Pd during edge phase
__device__ float g_VH[N_NODES * HDIM];     // reused as Ps during edge phase
__device__ float g_mi[N_NODES * HDIM];
__device__ float g_accum[N_NODES * 3];
__device__ float g_mij[N_EDGES * HDIM];
__device__ float g_partE[2 * EDGE_TILES * HDIM];  // edge BN partials
__device__ float g_partN[2 * 160 * HDIM];         // node BN partials
__device__ float g_muinv[2 * HDIM];

__device__ __forceinline__ float silu_f(float x) { return x / (1.0f + expf(-x)); }
__device__ __forceinline__ float elu_f(float x)  { return x > 0.0f ? x : (expf(x) - 1.0f); }

__device__ __forceinline__ ull fma2(ull a, ull b, ull c) {
    ull d;
    asm("fma.rn.f32x2 %0, %1, %2, %3;" : "=l"(d) : "l"(a), "l"(b), "l"(c));
    return d;
}
__device__ __forceinline__ float2 unpk(ull v) {
    unsigned lo, hi;
    asm("mov.b64 {%0,%1}, %2;" : "=r"(lo), "=r"(hi) : "l"(v));
    return make_float2(__uint_as_float(lo), __uint_as_float(hi));
}
__device__ __forceinline__ ull dup2(float a) {
    ull d;
    asm("mov.b64 %0, {%1,%1};" : "=l"(d) : "f"(a));
    return d;
}
__device__ __forceinline__ void red_add_v4(float* addr, float4 v) {
    asm volatile("red.global.add.v4.f32 [%0], {%1,%2,%3,%4};"
                 :: "l"(addr), "f"(v.x), "f"(v.y), "f"(v.z), "f"(v.w)
                 : "memory");
}

// Ts tile addressing: row stride 132 floats + 16B row-group swizzle
__device__ __forceinline__ int ts_off(int r, int c) {
    return r * 132 + ((r >> 3) & 1) * 4 + c;
}

// micro-GEMM over one 16-k slab: acc[8 rows][4 col-pairs] += Ts-col-slice * Bs
__device__ __forceinline__ void gemm_tile(ull (&acc)[8][4], const float* Ts,
                                          const float* Bs, int kbase,
                                          int row0, int col0)
{
    const float* arow = Ts + row0 * 132 + ((row0 >> 3) & 1) * 4 + kbase;
#pragma unroll
    for (int kk = 0; kk < 16; kk++) {
        const float* bp = Bs + kk * 132 + col0;
        ulonglong2 b01 = *(const ulonglong2*)bp;
        ulonglong2 b23 = *(const ulonglong2*)(bp + 4);
#pragma unroll
        for (int i = 0; i < 8; i++) {
            ull av = dup2(arow[i * 132 + kk]);
            acc[i][0] = fma2(av, b01.x, acc[i][0]);
            acc[i][1] = fma2(av, b01.y, acc[i][1]);
            acc[i][2] = fma2(av, b23.x, acc[i][2]);
            acc[i][3] = fma2(av, b23.y, acc[i][3]);
        }
    }
}

// ---------------- fused edge pipeline (per layer) ----------------
__global__ __launch_bounds__(256, 2)
void edge_fused_k(const int* __restrict__ srcv, const int* __restrict__ dstv,
                  const float* __restrict__ ee,
                  const float* __restrict__ Ps, const float* __restrict__ Pd,
                  const float* __restrict__ We1_tail,
                  const float* __restrict__ be1,
                  const float* __restrict__ We2, const float* __restrict__ be2,
                  const float* __restrict__ Wx1, const float* __restrict__ bx1,
                  const float* __restrict__ Wx2, const float* __restrict__ bx2,
                  int write_mij)
{
    extern __shared__ float smf[];
    float* Ts    = smf;                   // 16896
    float* Bs    = smf + 16896;           // 4224
    float* wex   = smf + 21120;           // 384
    float* be1s  = smf + 21504;           // 128
    float* wx2s  = smf + 21632;           // 384
    float* bx2s  = smf + 22016;           // 4
    float* diffs = smf + 22020;           // 384
    float* dists = smf + 22404;           // 128
    float* ee0s  = smf + 22532;           // 128
    float* ee1s  = smf + 22660;           // 128
    int*   dsts  = (int*)(smf + 22788);   // 128
    float* es    = smf + 22916;           // 256 : BN partial stats

    const int tid  = threadIdx.x;
    const int m0   = blockIdx.x * 128;
    const int brow = tid >> 4;
    const int bcol = (tid & 15) * 8;
    const int row0 = (tid >> 4) * 8;
    const int col0 = (tid & 15) * 8;

    // ---- phase 0 ----
    if (tid < 128) {
        int mm = m0 + tid;
        int s = srcv[mm], d = dstv[mm];
        float dx = g_coords[d * 3 + 0] - g_coords[s * 3 + 0];
        float dy = g_coords[d * 3 + 1] - g_coords[s * 3 + 1];
        float dz = g_coords[d * 3 + 2] - g_coords[s * 3 + 2];
        diffs[tid * 3 + 0] = dx;
        diffs[tid * 3 + 1] = dy;
        diffs[tid * 3 + 2] = dz;
        dists[tid] = sqrtf(dx * dx + dy * dy + dz * dz);
        dsts[tid] = d;
        ee0s[tid] = ee[mm * 2 + 0];
        ee1s[tid] = ee[mm * 2 + 1];
    }
    es[tid] = 0.f;
    for (int i = tid; i < 384; i += 256) { wex[i] = We1_tail[i]; wx2s[i] = Wx2[i]; }
    if (tid < 128) be1s[tid] = be1[tid];
    if (tid < 3)   bx2s[tid] = bx2[tid];
    __syncthreads();

    // ---- phase 1: T1 = silu(Ps[src] + Pd[dst] + dist*w + ee@W + be1) ----
    {
        const int r  = tid >> 1;
        const int mm = m0 + r;
        const int s  = srcv[mm];
        const int d  = dstv[mm];
        const float di = dists[r], e0 = ee0s[r], e1 = ee1s[r];
        const int cb = (tid & 1) * 64;
        const float* psp = Ps + (size_t)s * 128;
        const float* pdp = Pd + (size_t)d * 128;
#pragma unroll 4
        for (int c = cb; c < cb + 64; c += 4) {
            float4 a = *(const float4*)(psp + c);
            float4 b = *(const float4*)(pdp + c);
            float4 o;
            o.x = silu_f(a.x + b.x + di * wex[c+0] + e0 * wex[128+c+0] + e1 * wex[256+c+0] + be1s[c+0]);
            o.y = silu_f(a.y + b.y + di * wex[c+1] + e0 * wex[128+c+1] + e1 * wex[256+c+1] + be1s[c+1]);
            o.z = silu_f(a.z + b.z + di * wex[c+2] + e0 * wex[128+c+2] + e1 * wex[256+c+2] + be1s[c+2]);
            o.w = silu_f(a.w + b.w + di * wex[c+3] + e0 * wex[128+c+3] + e1 * wex[256+c+3] + be1s[c+3]);
            *(float4*)(Ts + ts_off(r, c)) = o;
        }
    }
    __syncthreads();

    auto loadB8 = [&](const float* W, int gk, float* v) {
        float4 x0 = *(const float4*)(W + (size_t)gk * 128 + bcol);
        float4 x1 = *(const float4*)(W + (size_t)gk * 128 + bcol + 4);
        v[0] = x0.x; v[1] = x0.y; v[2] = x0.z; v[3] = x0.w;
        v[4] = x1.x; v[5] = x1.y; v[6] = x1.z; v[7] = x1.w;
    };
    auto storeB = [&](int buf, const float* v) {
        float* base = Bs + buf * 2112 + brow * 132 + bcol;
        *(float4*)(base)     = make_float4(v[0], v[1], v[2], v[3]);
        *(float4*)(base + 4) = make_float4(v[4], v[5], v[6], v[7]);
    };

    ull acc[8][4];

    // ---- phase 2: mij = silu(T1 @ We2 + be2) ----
#pragma unroll
    for (int i = 0; i < 8; i++)
#pragma unroll
        for (int j = 0; j < 4; j++) acc[i][j] = 0ULL;
    {
        float vb[8];
        loadB8(We2, brow, vb); storeB(0, vb);
    }
    __syncthreads();
    int buf = 0;
    for (int kt = 0; kt < 8; kt++) {
        float nb[8];
        const bool pre = (kt < 7);
        if (pre) loadB8(We2, (kt + 1) * 16 + brow, nb);
        gemm_tile(acc, Ts, Bs + buf * 2112, kt * 16, row0, col0);
        if (pre) storeB(buf ^ 1, nb);
        __syncthreads();
        buf ^= 1;
    }
    {
        float b[8];
        *(float4*)b       = *(const float4*)(be2 + col0);
        *(float4*)(b + 4) = *(const float4*)(be2 + col0 + 4);
        float cs[8], cq[8];
#pragma unroll
        for (int j = 0; j < 8; j++) { cs[j] = 0.f; cq[j] = 0.f; }
#pragma unroll
        for (int i = 0; i < 8; i++) {
            float mv[8];
#pragma unroll
            for (int jp = 0; jp < 4; jp++) {
                float2 c = unpk(acc[i][jp]);
                mv[2 * jp]     = silu_f(c.x + b[2 * jp]);
                mv[2 * jp + 1] = silu_f(c.y + b[2 * jp + 1]);
            }
            const int d = dsts[row0 + i];
            red_add_v4(&g_mi[(size_t)d * 128 + col0],
                       make_float4(mv[0], mv[1], mv[2], mv[3]));
            red_add_v4(&g_mi[(size_t)d * 128 + col0 + 4],
                       make_float4(mv[4], mv[5], mv[6], mv[7]));
            if (write_mij) {
                float* gp = g_mij + (size_t)(m0 + row0 + i) * 128 + col0;
                *(float4*)gp       = make_float4(mv[0], mv[1], mv[2], mv[3]);
                *(float4*)(gp + 4) = make_float4(mv[4], mv[5], mv[6], mv[7]);
#pragma unroll
                for (int j = 0; j < 8; j++) {
                    float e = elu_f(mv[j]);
                    cs[j] += e;
                    cq[j] += e * e;
                }
            }
            float* trow = Ts + ts_off(row0 + i, col0);
            *(float4*)trow       = make_float4(mv[0], mv[1], mv[2], mv[3]);
            *(float4*)(trow + 4) = make_float4(mv[4], mv[5], mv[6], mv[7]);
        }
        if (write_mij) {
#pragma unroll
            for (int j = 0; j < 8; j++) {
                atomicAdd(&es[col0 + j], cs[j]);
                atomicAdd(&es[128 + col0 + j], cq[j]);
            }
        }
    }
    __syncthreads();
    if (write_mij && tid < 128) {
        g_partE[blockIdx.x * 128 + tid] = es[tid];
        g_partE[(EDGE_TILES + blockIdx.x) * 128 + tid] = es[128 + tid];
    }

    // ---- phase 3: T2 = silu(mij @ Wx1 + bx1) ----
#pragma unroll
    for (int i = 0; i < 8; i++)
#pragma unroll
        for (int j = 0; j < 4; j++) acc[i][j] = 0ULL;
    {
        float vb[8];
        loadB8(Wx1, brow, vb); storeB(0, vb);
    }
    __syncthreads();
    buf = 0;
    for (int kt = 0; kt < 8; kt++) {
        float nb[8];
        const bool pre = (kt < 7);
        if (pre) loadB8(Wx1, (kt + 1) * 16 + brow, nb);
        gemm_tile(acc, Ts, Bs + buf * 2112, kt * 16, row0, col0);
        if (pre) storeB(buf ^ 1, nb);
        __syncthreads();
        buf ^= 1;
    }
    {
        float b[8];
        *(float4*)b       = *(const float4*)(bx1 + col0);
        *(float4*)(b + 4) = *(const float4*)(bx1 + col0 + 4);
#pragma unroll
        for (int i = 0; i < 8; i++) {
            float* trow = Ts + ts_off(row0 + i, col0);
#pragma unroll
            for (int jp = 0; jp < 4; jp++) {
                float2 c = unpk(acc[i][jp]);
                trow[2 * jp]     = silu_f(c.x + b[2 * jp]);
                trow[2 * jp + 1] = silu_f(c.y + b[2 * jp + 1]);
            }
        }
    }
    __syncthreads();

    // ---- phase 4: px = T2 @ Wx2 + bx2 ; coord scatter ----
    if (tid < 128) {
        const float* trow = Ts + ts_off(tid, 0);
        float p0 = 0.f, p1 = 0.f, p2 = 0.f;
#pragma unroll 8
        for (int k = 0; k < 128; k++) {
            float t = trow[k];
            p0 += t * wx2s[k * 3 + 0];
            p1 += t * wx2s[k * 3 + 1];
            p2 += t * wx2s[k * 3 + 2];
        }
        p0 += bx2s[0]; p1 += bx2s[1]; p2 += bx2s[2];
        const int d = dsts[tid];
        atomicAdd(&g_accum[d * 3 + 0], diffs[tid * 3 + 0] * p0);
        atomicAdd(&g_accum[d * 3 + 1], diffs[tid * 3 + 1] * p1);
        atomicAdd(&g_accum[d * 3 + 2], diffs[tid * 3 + 2] * p2);
    }
}

// ---------------- node GEMMs: BM=64, BN=128, full-chip grids ----------------
enum { MODE_PLAIN = 0, MODE_CAT = 2 };

// grid (ceil(M/64), nInst). Instance i uses W[i], C[i] (Wa/Ca vs Wb/Cb).
template <int MODE, bool DO_SILU, bool HAS_BIAS, bool DO_STATS>
__global__ __launch_bounds__(256) void gemm64_k(
    const float* __restrict__ A, const float* __restrict__ A2,
    const float* __restrict__ Wa, const float* __restrict__ Wb,
    const float* __restrict__ bias,
    float* __restrict__ Ca, float* __restrict__ Cb,
    int M, int K, float* __restrict__ part, int nblk)
{
    __shared__ float As[16][68];
    __shared__ float Bs[16][132];
    __shared__ float sstat[256];

    const float* W = (blockIdx.y == 0) ? Wa : Wb;
    float*       C = (blockIdx.y == 0) ? Ca : Cb;

    const int tid  = threadIdx.x;
    const int m0   = blockIdx.x * 64;
    const int arow = tid >> 2;           // 0..63
    const int akb  = (tid & 3) * 4;      // 0,4,8,12
    const int brow = tid >> 4;
    const int bcol = (tid & 15) * 8;
    const int gm   = m0 + arow;
    const bool mval = (gm < M);
    const int row0 = (tid >> 4) * 4;
    const int col0 = (tid & 15) * 8;

    if (DO_STATS) sstat[tid] = 0.f;

    float acc[4][8];
#pragma unroll
    for (int i = 0; i < 4; i++)
#pragma unroll
        for (int j = 0; j < 8; j++) acc[i][j] = 0.f;

    const int nk = K >> 4;   // K is 128 or 256
    for (int kt = 0; kt < nk; kt++) {
        const int kbase = kt * 16;
        {
            const float* wp = W + (size_t)(kbase + brow) * 128 + bcol;
#pragma unroll
            for (int i = 0; i < 8; i++) Bs[brow][bcol + i] = wp[i];
        }
#pragma unroll
        for (int i = 0; i < 4; i++) {
            const int gk = kbase + akb + i;
            float v = 0.f;
            if (mval) {
                if (MODE == MODE_PLAIN) v = A[(size_t)gm * K + gk];
                else v = (gk < 128) ? A[(size_t)gm * 128 + gk]
                                    : A2[(size_t)gm * 128 + (gk - 128)];
            }
            As[akb + i][arow] = v;
        }
        __syncthreads();
#pragma unroll
        for (int kk = 0; kk < 16; kk++) {
            float4 a = *(const float4*)&As[kk][row0];
            float4 b0 = *(const float4*)&Bs[kk][col0];
            float4 b1 = *(const float4*)&Bs[kk][col0 + 4];
            float av[4] = {a.x, a.y, a.z, a.w};
            float bv[8] = {b0.x, b0.y, b0.z, b0.w, b1.x, b1.y, b1.z, b1.w};
#pragma unroll
            for (int i = 0; i < 4; i++)
#pragma unroll
                for (int j = 0; j < 8; j++) acc[i][j] += av[i] * bv[j];
        }
        __syncthreads();
    }

    float cs[8], cq[8];
    if (DO_STATS) {
#pragma unroll
        for (int j = 0; j < 8; j++) { cs[j] = 0.f; cq[j] = 0.f; }
    }
#pragma unroll
    for (int i = 0; i < 4; i++) {
        const int mm = m0 + row0 + i;
        if (mm < M) {
            float* cp = C + (size_t)mm * 128 + col0;
#pragma unroll
            for (int j = 0; j < 8; j++) {
                float c = acc[i][j] + (HAS_BIAS ? bias[col0 + j] : 0.f);
                if (DO_SILU) c = silu_f(c);
                cp[j] = c;
                if (DO_STATS) {
                    float e = elu_f(c);
                    cs[j] += e;
                    cq[j] += e * e;
                }
            }
        }
    }
    if (DO_STATS) {
        __syncthreads();
#pragma unroll
        for (int j = 0; j < 8; j++) {
            atomicAdd(&sstat[col0 + j], cs[j]);
            atomicAdd(&sstat[128 + col0 + j], cq[j]);
        }
        __syncthreads();
        if (tid < 128) {
            part[blockIdx.x * 128 + tid] = sstat[tid];
            part[(nblk + blockIdx.x) * 128 + tid] = sstat[128 + tid];
        }
    }
}

// ---------------- small kernels ----------------
__global__ void init_nodes_k(const float* __restrict__ emb,
                             const float* __restrict__ Wn,
                             const float* __restrict__ bn)
{
    int idx = blockIdx.x * blockDim.x + threadIdx.x;
    if (idx < N_NODES * 3) g_coords[idx] = emb[idx];
    if (idx < N_NODES * HDIM) {
        int n = idx >> 7, j = idx & 127;
        g_V[idx] = emb[n * 3 + 0] * Wn[0 * 128 + j]
                 + emb[n * 3 + 1] * Wn[1 * 128 + j]
                 + emb[n * 3 + 2] * Wn[2 * 128 + j]
                 + bn[j];
    }
}

__global__ void zero_k(float* __restrict__ p, int n)
{
    int idx = blockIdx.x * blockDim.x + threadIdx.x;
    if (idx < n) p[idx] = 0.f;
}

__global__ void coords_update_k()
{
    int idx = blockIdx.x * blockDim.x + threadIdx.x;
    if (idx < N_NODES * 3)
        g_coords[idx] += g_accum[idx] * (1.0f / (float)(N_NODES - 1));
}

// ---------------- BatchNorm finalize ----------------
__global__ void bn_stats2_k(const float* __restrict__ part, int B, int M)
{
    int j = threadIdx.x;
    double s = 0.0, q = 0.0;
    for (int b = 0; b < B; b++) {
        s += (double)part[b * 128 + j];
        q += (double)part[(B + b) * 128 + j];
    }
    double mu  = s / (double)M;
    double var = q / (double)M - mu * mu;
    g_muinv[j]       = (float)mu;
    g_muinv[128 + j] = (float)rsqrt(var + (double)BN_EPS);
}

__global__ void bn_norm_k(const float* __restrict__ X,
                          const float* __restrict__ gam,
                          const float* __restrict__ bet,
                          float* __restrict__ out, int M)
{
    int idx = blockIdx.x * blockDim.x + threadIdx.x;
    if (idx >= M * 128) return;
    int j = idx & 127;
    float x = elu_f(X[idx]);
    out[idx] = gam[j] * (x - g_muinv[j]) * g_muinv[128 + j] + bet[j];
}

// ---------------- host launcher ----------------
static void* sym_addr(const void* sym)
{
    void* p = nullptr;
    cudaGetSymbolAddress(&p, sym);
    return p;
}

extern "C" void kernel_launch(void* const* d_in, const int* in_sizes, int n_in,
                              void* d_out, int out_size)
{
    (void)in_sizes; (void)n_in; (void)out_size;

    const float* emb_nodes = (const float*)d_in[0];
    const float* emb_edges = (const float*)d_in[1];
    const int*   edge_idx  = (const int*)d_in[2];
    const float* pre_Wn    = (const float*)d_in[3];
    const float* pre_bn    = (const float*)d_in[4];
    const float* We1 = (const float*)d_in[7];
    const float* be1 = (const float*)d_in[8];
    const float* We2 = (const float*)d_in[9];
    const float* be2 = (const float*)d_in[10];
    const float* Wx1 = (const float*)d_in[11];
    const float* bx1 = (const float*)d_in[12];
    const float* Wx2 = (const float*)d_in[13];
    const float* bx2 = (const float*)d_in[14];
    const float* Wh1 = (const float*)d_in[15];
    const float* bh1 = (const float*)d_in[16];
    const float* Wh2 = (const float*)d_in[17];
    const float* bh2 = (const float*)d_in[18];
    const float* gam_n = (const float*)d_in[19];
    const float* bet_n = (const float*)d_in[20];
    const float* gam_e = (const float*)d_in[21];
    const float* bet_e = (const float*)d_in[22];

    float* out  = (float*)d_out;
    float* outV = out;
    float* outE = out + (size_t)N_NODES * HDIM;

    const int* srcv = edge_idx;
    const int* dstv = edge_idx + N_EDGES;

    float* pV     = (float*)sym_addr(g_V);
    float* pVraw  = (float*)sym_addr(g_Vraw);
    float* pVH    = (float*)sym_addr(g_VH);
    float* pMi    = (float*)sym_addr(g_mi);
    float* pAcc   = (float*)sym_addr(g_accum);
    float* pMij   = (float*)sym_addr(g_mij);
    float* pPartE = (float*)sym_addr(g_partE);
    float* pPartN = (float*)sym_addr(g_partN);

    const int EDGE_SMEM = 23172 * 4;  // 92688 B
    cudaFuncSetAttribute(edge_fused_k,
                         cudaFuncAttributeMaxDynamicSharedMemorySize, EDGE_SMEM);

    const int TB = 256;
    const int nodeHBlocks = (N_NODES * HDIM + TB - 1) / TB;
    const int edgeHBlocks = (N_EDGES * HDIM + TB - 1) / TB;

    init_nodes_k<<<nodeHBlocks, TB>>>(emb_nodes, pre_Wn, pre_bn);

    for (int l = 0; l < NLAYERS; l++) {
        const float* We1l = We1 + (size_t)l * 259 * 128;
        const float* be1l = be1 + l * 128;
        const float* We2l = We2 + (size_t)l * 128 * 128;
        const float* be2l = be2 + l * 128;
        const float* Wx1l = Wx1 + (size_t)l * 128 * 128;
        const float* bx1l = bx1 + l * 128;
        const float* Wx2l = Wx2 + (size_t)l * 128 * 3;
        const float* bx2l = bx2 + l * 3;
        const float* Wh1l = Wh1 + (size_t)l * 256 * 128;
        const float* bh1l = bh1 + l * 128;
        const float* Wh2l = Wh2 + (size_t)l * 128 * 128;
        const float* bh2l = bh2 + l * 128;

        zero_k<<<nodeHBlocks, TB>>>(pMi, N_NODES * HDIM);
        zero_k<<<(N_NODES * 3 + TB - 1) / TB, TB>>>(pAcc, N_NODES * 3);

        // Ps = V @ We1[0:128] -> g_VH ; Pd = V @ We1[128:256] -> g_Vraw
        gemm64_k<MODE_PLAIN, false, false, false>
            <<<dim3(NODE_TILES, 2), 256>>>(
                pV, nullptr, We1l, We1l + 128 * 128, nullptr,
                pVH, pVraw, N_NODES, 128, nullptr, 0);

        edge_fused_k<<<EDGE_TILES, 256, EDGE_SMEM>>>(
            srcv, dstv, emb_edges, pVH, pVraw,
            We1l + 256 * 128, be1l,
            We2l, be2l, Wx1l, bx1l, Wx2l, bx2l,
            (l == NLAYERS - 1) ? 1 : 0);

        coords_update_k<<<(N_NODES * 3 + TB - 1) / TB, TB>>>();

        // VH = silu([V, mi] @ Wh1 + bh1)
        gemm64_k<MODE_CAT, true, true, false>
            <<<dim3(NODE_TILES, 1), 256>>>(
                pV, pMi, Wh1l, Wh1l, bh1l,
                pVH, pVH, N_NODES, 256, nullptr, 0);
        // Vraw = VH @ Wh2 + bh2, with fused BN partial stats
        gemm64_k<MODE_PLAIN, false, true, true>
            <<<dim3(NODE_TILES, 1), 256>>>(
                pVH, nullptr, Wh2l, Wh2l, bh2l,
                pVraw, pVraw, N_NODES, 128, pPartN, NODE_TILES);

        bn_stats2_k<<<1, 128>>>(pPartN, NODE_TILES, N_NODES);
        float* vdst = (l == NLAYERS - 1) ? outV : pV;
        bn_norm_k<<<nodeHBlocks, TB>>>(pVraw, gam_n + l * 128, bet_n + l * 128,
                                       vdst, N_NODES);

        if (l == NLAYERS - 1) {
            bn_stats2_k<<<1, 128>>>(pPartE, EDGE_TILES, N_EDGES);
            bn_norm_k<<<edgeHBlocks, TB>>>(pMij, gam_e + l * 128, bet_e + l * 128,
                                           outE, N_EDGES);
        }
    }
}